// round 5
// baseline (speedup 1.0000x reference)
#include <cuda_runtime.h>
#include <cstdint>

#define NN 50000
#define EE 800000
#define INF 128
#define HC 128
#define HH 8
#define ED 16

#define NPAD 50176            // 196 * 256, >= NN+1

// ---- scratch (device globals; no allocation allowed) ----
__device__ __align__(16) float g_q[NN * HC];
__device__ __align__(16) float g_k[NN * HC];
__device__ __align__(16) float g_v[NN * HC];
__device__ int g_cnt[NPAD];        // per-dst degree histogram (zero-padded)
__device__ int g_rowptr[NPAD];     // exclusive prefix sum (rowptr[NN] valid)
__device__ int g_wcnt[NN];         // write cursors for permute
__device__ int g_blk[256];         // per-block sums for scan
__device__ int g_eid[EE];          // edge ids sorted by dst

// ---------------------------------------------------------------------------
// zero degree histogram (graph replays need this every call)
// ---------------------------------------------------------------------------
__global__ void zero_kernel() {
    int i = blockIdx.x * blockDim.x + threadIdx.x;
    if (i < NPAD) g_cnt[i] = 0;
}

// ---------------------------------------------------------------------------
// histogram of dst
// ---------------------------------------------------------------------------
__global__ void hist_kernel(const int* __restrict__ ei) {
    int e = blockIdx.x * blockDim.x + threadIdx.x;
    if (e < EE) atomicAdd(&g_cnt[ei[EE + e]], 1);
}

// ---------------------------------------------------------------------------
// 3-phase exclusive scan over g_cnt[NPAD] -> g_rowptr
// ---------------------------------------------------------------------------
__global__ void scan1_kernel() {
    __shared__ int s[256];
    int t = threadIdx.x;
    int i = blockIdx.x * 256 + t;
    int v = g_cnt[i];
    s[t] = v;
    __syncthreads();
    #pragma unroll
    for (int off = 1; off < 256; off <<= 1) {
        int u = (t >= off) ? s[t - off] : 0;
        __syncthreads();
        s[t] += u;
        __syncthreads();
    }
    g_rowptr[i] = s[t] - v;                 // exclusive within block
    if (t == 255) g_blk[blockIdx.x] = s[255];
}

__global__ void scan2_kernel() {
    __shared__ int s[256];
    int t = threadIdx.x;
    int v = (t < 196) ? g_blk[t] : 0;
    s[t] = v;
    __syncthreads();
    #pragma unroll
    for (int off = 1; off < 256; off <<= 1) {
        int u = (t >= off) ? s[t - off] : 0;
        __syncthreads();
        s[t] += u;
        __syncthreads();
    }
    if (t < 196) g_blk[t] = s[t] - v;       // exclusive block offsets
}

__global__ void scan3_kernel() {
    int i = blockIdx.x * blockDim.x + threadIdx.x;
    if (i < NPAD) {
        int v = g_rowptr[i] + g_blk[i >> 8];
        g_rowptr[i] = v;
        if (i < NN) g_wcnt[i] = v;
    }
}

// ---------------------------------------------------------------------------
// permute: bucket edge ids by dst
// ---------------------------------------------------------------------------
__global__ void permute_kernel(const int* __restrict__ ei) {
    int e = blockIdx.x * blockDim.x + threadIdx.x;
    if (e < EE) {
        int dst = ei[EE + e];
        int pos = atomicAdd(&g_wcnt[dst], 1);
        g_eid[pos] = e;
    }
}

// ---------------------------------------------------------------------------
// Fused 4x GEMM: y = x @ W + b for W in {w_q, w_k, w_v, w_skip}
// blockIdx.y selects the matrix; skip result goes straight into d_out.
// Tile: M=128, N=128, K chunked by 32. 256 threads, 8x8 microtile/thread.
// ---------------------------------------------------------------------------
__global__ __launch_bounds__(256) void gemm_kernel(
    const float* __restrict__ x,
    const float* __restrict__ wq, const float* __restrict__ bq,
    const float* __restrict__ wk, const float* __restrict__ bk,
    const float* __restrict__ wv, const float* __restrict__ bv,
    const float* __restrict__ ws, const float* __restrict__ bs,
    float* __restrict__ out)
{
    __shared__ float As[32][132];   // transposed x tile: As[k][m], padded
    __shared__ float Bs[32][128];   // Bs[k][n]

    const float* W; const float* B; float* O;
    switch (blockIdx.y) {
        case 0:  W = wq; B = bq; O = g_q; break;
        case 1:  W = wk; B = bk; O = g_k; break;
        case 2:  W = wv; B = bv; O = g_v; break;
        default: W = ws; B = bs; O = out; break;
    }

    int tid = threadIdx.x;
    int tx = tid & 15, ty = tid >> 4;
    int rowBase = blockIdx.x * 128;

    float acc[8][8];
    #pragma unroll
    for (int i = 0; i < 8; i++)
        #pragma unroll
        for (int j = 0; j < 8; j++) acc[i][j] = 0.f;

    for (int k0 = 0; k0 < INF; k0 += 32) {
        #pragma unroll
        for (int i = 0; i < 16; i++) {
            int idx = tid + i * 256;       // 0..4095
            int r  = idx >> 5;             // row within tile
            int kk = idx & 31;             // k within chunk
            int gr = rowBase + r;
            As[kk][r] = (gr < NN) ? x[gr * INF + k0 + kk] : 0.f;
        }
        #pragma unroll
        for (int i = 0; i < 16; i++) {
            int idx = tid + i * 256;
            int kk = idx >> 7;
            int n  = idx & 127;
            Bs[kk][n] = W[(k0 + kk) * HC + n];
        }
        __syncthreads();

        #pragma unroll
        for (int kk = 0; kk < 32; kk++) {
            float4 a0 = *(const float4*)&As[kk][ty * 8];
            float4 a1 = *(const float4*)&As[kk][ty * 8 + 4];
            float4 b0 = *(const float4*)&Bs[kk][tx * 8];
            float4 b1 = *(const float4*)&Bs[kk][tx * 8 + 4];
            float av[8] = {a0.x, a0.y, a0.z, a0.w, a1.x, a1.y, a1.z, a1.w};
            float bw[8] = {b0.x, b0.y, b0.z, b0.w, b1.x, b1.y, b1.z, b1.w};
            #pragma unroll
            for (int i = 0; i < 8; i++)
                #pragma unroll
                for (int j = 0; j < 8; j++)
                    acc[i][j] += av[i] * bw[j];
        }
        __syncthreads();
    }

    #pragma unroll
    for (int i = 0; i < 8; i++) {
        int gr = rowBase + ty * 8 + i;
        if (gr < NN) {
            #pragma unroll
            for (int j = 0; j < 8; j += 4) {
                float4 o;
                o.x = acc[i][j + 0] + B[tx * 8 + j + 0];
                o.y = acc[i][j + 1] + B[tx * 8 + j + 1];
                o.z = acc[i][j + 2] + B[tx * 8 + j + 2];
                o.w = acc[i][j + 3] + B[tx * 8 + j + 3];
                *(float4*)&O[gr * HC + tx * 8 + j] = o;
            }
        }
    }
}

// ---------------------------------------------------------------------------
// Gather kernel: one warp per dst node. Walk the node's CSR edge list,
// accumulate numerator (4 channels/lane) and denominator in registers,
// single non-atomic RMW into out. w_e slice lives in registers (loop-inv).
//   e_c = edge_attr[eid] @ w_e[:,c]
//   p   = exp(q[dst]·(k[src]+e)/4)     (shift-invariant softmax, bounded)
//   num += p*(v[src]+e);  den += p
//   out[dst] += num/(den+1e-16)
// ---------------------------------------------------------------------------
__global__ __launch_bounds__(256, 2) void gather_kernel(
    const int* __restrict__ ei,
    const float* __restrict__ ea,
    const float* __restrict__ we,
    float* __restrict__ out)
{
    int lane = threadIdx.x & 31;
    int node = (blockIdx.x * 256 + threadIdx.x) >> 5;
    if (node >= NN) return;
    int c0 = lane << 2;        // 4 channels per lane

    // loop-invariant w_e slice: 16 x float4 in registers (coalesced load)
    float4 rw[ED];
    #pragma unroll
    for (int i = 0; i < ED; i++)
        rw[i] = *(const float4*)&we[i * HC + c0];

    int beg = g_rowptr[node];
    int end = g_rowptr[node + 1];

    float4 q4 = *(const float4*)&g_q[node * HC + c0];
    float nx = 0.f, ny = 0.f, nz = 0.f, nw4 = 0.f;
    float den = 0.f;

    for (int i = beg; i < end; i++) {
        int eid = g_eid[i];
        int src = ei[eid];

        float mea = (lane < ED) ? ea[eid * ED + lane] : 0.f;
        float ex = 0.f, ey = 0.f, ez = 0.f, ew = 0.f;
        #pragma unroll
        for (int t = 0; t < ED; t++) {
            float a = __shfl_sync(0xffffffffu, mea, t);
            ex += a * rw[t].x; ey += a * rw[t].y;
            ez += a * rw[t].z; ew += a * rw[t].w;
        }

        float4 k4 = *(const float4*)&g_k[src * HC + c0];
        float s = q4.x * (k4.x + ex) + q4.y * (k4.y + ey)
                + q4.z * (k4.z + ez) + q4.w * (k4.w + ew);
        s += __shfl_xor_sync(0xffffffffu, s, 1);
        s += __shfl_xor_sync(0xffffffffu, s, 2);

        float p = __expf(s * 0.25f);   // 1/sqrt(C), C=16

        float4 v4 = *(const float4*)&g_v[src * HC + c0];
        nx += (v4.x + ex) * p;
        ny += (v4.y + ey) * p;
        nz += (v4.z + ez) * p;
        nw4 += (v4.w + ew) * p;
        den += p;
    }

    float inv = 1.f / (den + 1e-16f);
    float4 o = *(float4*)&out[(size_t)node * HC + c0];
    o.x += nx * inv; o.y += ny * inv;
    o.z += nz * inv; o.w += nw4 * inv;
    *(float4*)&out[(size_t)node * HC + c0] = o;
}

// ---------------------------------------------------------------------------
extern "C" void kernel_launch(void* const* d_in, const int* in_sizes, int n_in,
                              void* d_out, int out_size)
{
    const float* x  = (const float*)d_in[0];
    const int*   ei = (const int*)d_in[1];
    const float* ea = (const float*)d_in[2];
    const float* wq = (const float*)d_in[3];
    const float* bq = (const float*)d_in[4];
    const float* wk = (const float*)d_in[5];
    const float* bk = (const float*)d_in[6];
    const float* wv = (const float*)d_in[7];
    const float* bv = (const float*)d_in[8];
    const float* we = (const float*)d_in[9];
    const float* ws = (const float*)d_in[10];
    const float* bs = (const float*)d_in[11];
    float* out = (float*)d_out;

    // CSR build (by dst)
    zero_kernel<<<NPAD / 256, 256>>>();
    hist_kernel<<<(EE + 255) / 256, 256>>>(ei);
    scan1_kernel<<<196, 256>>>();
    scan2_kernel<<<1, 256>>>();
    scan3_kernel<<<NPAD / 256, 256>>>();
    permute_kernel<<<(EE + 255) / 256, 256>>>(ei);

    // projections
    dim3 g0(391, 4);                       // ceil(50000/128) x 4 matrices
    gemm_kernel<<<g0, 256>>>(x, wq, bq, wk, bk, wv, bv, ws, bs, out);

    // attention gather
    gather_kernel<<<(NN * 32 + 255) / 256, 256>>>(ei, ea, we, out);
}

// round 6
// speedup vs baseline: 1.1881x; 1.1881x over previous
#include <cuda_runtime.h>
#include <cstdint>

#define NN 50000
#define EE 800000
#define INF 128
#define HC 128
#define HH 8
#define ED 16

#define NPAD 50176            // 196 * 256, >= NN+1
#define CHUNK 16              // sorted edges per warp

// ---- scratch (device globals; no allocation allowed) ----
__device__ __align__(16) float g_q[NN * HC];
__device__ __align__(16) float g_k[NN * HC];
__device__ __align__(16) float g_v[NN * HC];
__device__ __align__(16) float g_attn[NN * HC];   // unnormalized numerator
__device__ __align__(16) float g_sum[NN * HH];    // softmax denominator
__device__ int g_cnt[NPAD];        // per-dst degree histogram (zero-padded)
__device__ int g_rowptr[NPAD];     // exclusive prefix sum
__device__ int g_wcnt[NN];         // write cursors for permute
__device__ int g_blk[256];         // per-block sums for scan
__device__ __align__(16) int4 g_sde[EE];  // (src, dst, eid, 0) sorted by dst

// ---------------------------------------------------------------------------
// zero: histogram + numerator + denominator
// ---------------------------------------------------------------------------
__global__ void zero_kernel() {
    int i = blockIdx.x * blockDim.x + threadIdx.x;
    if (i < NPAD) g_cnt[i] = 0;
    int n4 = (NN * HC) / 4;
    if (i < n4) ((float4*)g_attn)[i] = make_float4(0.f, 0.f, 0.f, 0.f);
    if (i < NN * HH) g_sum[i] = 0.f;
}

// ---------------------------------------------------------------------------
// histogram of dst
// ---------------------------------------------------------------------------
__global__ void hist_kernel(const int* __restrict__ ei) {
    int e = blockIdx.x * blockDim.x + threadIdx.x;
    if (e < EE) atomicAdd(&g_cnt[ei[EE + e]], 1);
}

// ---------------------------------------------------------------------------
// 3-phase exclusive scan over g_cnt[NPAD] -> g_rowptr
// ---------------------------------------------------------------------------
__global__ void scan1_kernel() {
    __shared__ int s[256];
    int t = threadIdx.x;
    int i = blockIdx.x * 256 + t;
    int v = g_cnt[i];
    s[t] = v;
    __syncthreads();
    #pragma unroll
    for (int off = 1; off < 256; off <<= 1) {
        int u = (t >= off) ? s[t - off] : 0;
        __syncthreads();
        s[t] += u;
        __syncthreads();
    }
    g_rowptr[i] = s[t] - v;
    if (t == 255) g_blk[blockIdx.x] = s[255];
}

__global__ void scan2_kernel() {
    __shared__ int s[256];
    int t = threadIdx.x;
    int v = (t < 196) ? g_blk[t] : 0;
    s[t] = v;
    __syncthreads();
    #pragma unroll
    for (int off = 1; off < 256; off <<= 1) {
        int u = (t >= off) ? s[t - off] : 0;
        __syncthreads();
        s[t] += u;
        __syncthreads();
    }
    if (t < 196) g_blk[t] = s[t] - v;
}

__global__ void scan3_kernel() {
    int i = blockIdx.x * blockDim.x + threadIdx.x;
    if (i < NPAD) {
        int v = g_rowptr[i] + g_blk[i >> 8];
        g_rowptr[i] = v;
        if (i < NN) g_wcnt[i] = v;
    }
}

// ---------------------------------------------------------------------------
// permute: bucket (src,dst,eid) records by dst
// ---------------------------------------------------------------------------
__global__ void permute_kernel(const int* __restrict__ ei) {
    int e = blockIdx.x * blockDim.x + threadIdx.x;
    if (e < EE) {
        int src = ei[e];
        int dst = ei[EE + e];
        int pos = atomicAdd(&g_wcnt[dst], 1);
        g_sde[pos] = make_int4(src, dst, e, 0);
    }
}

// ---------------------------------------------------------------------------
// Fused 4x GEMM: y = x @ W + b for W in {w_q, w_k, w_v, w_skip}
// blockIdx.y selects the matrix; skip result goes straight into d_out.
// ---------------------------------------------------------------------------
__global__ __launch_bounds__(256) void gemm_kernel(
    const float* __restrict__ x,
    const float* __restrict__ wq, const float* __restrict__ bq,
    const float* __restrict__ wk, const float* __restrict__ bk,
    const float* __restrict__ wv, const float* __restrict__ bv,
    const float* __restrict__ ws, const float* __restrict__ bs,
    float* __restrict__ out)
{
    __shared__ float As[32][132];
    __shared__ float Bs[32][128];

    const float* W; const float* B; float* O;
    switch (blockIdx.y) {
        case 0:  W = wq; B = bq; O = g_q; break;
        case 1:  W = wk; B = bk; O = g_k; break;
        case 2:  W = wv; B = bv; O = g_v; break;
        default: W = ws; B = bs; O = out; break;
    }

    int tid = threadIdx.x;
    int tx = tid & 15, ty = tid >> 4;
    int rowBase = blockIdx.x * 128;

    float acc[8][8];
    #pragma unroll
    for (int i = 0; i < 8; i++)
        #pragma unroll
        for (int j = 0; j < 8; j++) acc[i][j] = 0.f;

    for (int k0 = 0; k0 < INF; k0 += 32) {
        #pragma unroll
        for (int i = 0; i < 16; i++) {
            int idx = tid + i * 256;
            int r  = idx >> 5;
            int kk = idx & 31;
            int gr = rowBase + r;
            As[kk][r] = (gr < NN) ? x[gr * INF + k0 + kk] : 0.f;
        }
        #pragma unroll
        for (int i = 0; i < 16; i++) {
            int idx = tid + i * 256;
            int kk = idx >> 7;
            int n  = idx & 127;
            Bs[kk][n] = W[(k0 + kk) * HC + n];
        }
        __syncthreads();

        #pragma unroll
        for (int kk = 0; kk < 32; kk++) {
            float4 a0 = *(const float4*)&As[kk][ty * 8];
            float4 a1 = *(const float4*)&As[kk][ty * 8 + 4];
            float4 b0 = *(const float4*)&Bs[kk][tx * 8];
            float4 b1 = *(const float4*)&Bs[kk][tx * 8 + 4];
            float av[8] = {a0.x, a0.y, a0.z, a0.w, a1.x, a1.y, a1.z, a1.w};
            float bw[8] = {b0.x, b0.y, b0.z, b0.w, b1.x, b1.y, b1.z, b1.w};
            #pragma unroll
            for (int i = 0; i < 8; i++)
                #pragma unroll
                for (int j = 0; j < 8; j++)
                    acc[i][j] += av[i] * bw[j];
        }
        __syncthreads();
    }

    #pragma unroll
    for (int i = 0; i < 8; i++) {
        int gr = rowBase + ty * 8 + i;
        if (gr < NN) {
            #pragma unroll
            for (int j = 0; j < 8; j += 4) {
                float4 o;
                o.x = acc[i][j + 0] + B[tx * 8 + j + 0];
                o.y = acc[i][j + 1] + B[tx * 8 + j + 1];
                o.z = acc[i][j + 2] + B[tx * 8 + j + 2];
                o.w = acc[i][j + 3] + B[tx * 8 + j + 3];
                *(float4*)&O[gr * HC + tx * 8 + j] = o;
            }
        }
    }
}

// ---------------------------------------------------------------------------
// Sorted-scatter edge kernel: each warp takes CHUNK consecutive dst-sorted
// edges, accumulates num/den in registers across same-dst runs, and flushes
// one red.global.add.v4 (+ scalar den red) per run boundary.
//   e_c = edge_attr[eid] @ w_e[:,c]    (w_e slice in registers)
//   p   = exp(q[dst]·(k[src]+e)/4)     (shift-invariant softmax, bounded)
// ---------------------------------------------------------------------------
__global__ __launch_bounds__(256, 2) void edge_sorted_kernel(
    const float* __restrict__ ea,
    const float* __restrict__ we)
{
    int lane = threadIdx.x & 31;
    int w = (blockIdx.x * 256 + threadIdx.x) >> 5;   // warp id
    int base = w * CHUNK;
    if (base >= EE) return;
    int end = (base + CHUNK < EE) ? base + CHUNK : EE;

    int c0 = lane << 2;        // 4 channels per lane
    int head = lane >> 2;      // 4 lanes per head (C=16)

    float4 rw[ED];
    #pragma unroll
    for (int i = 0; i < ED; i++)
        rw[i] = *(const float4*)&we[i * HC + c0];

    int cur_dst = -1;
    float4 q4 = make_float4(0.f, 0.f, 0.f, 0.f);
    float nx = 0.f, ny = 0.f, nz = 0.f, nw4 = 0.f, den = 0.f;

    for (int i = base; i < end; i++) {
        int4 sde = g_sde[i];               // uniform across warp
        int src = sde.x, dst = sde.y, eid = sde.z;

        if (dst != cur_dst) {
            if (cur_dst >= 0) {
                float* op = g_attn + (size_t)cur_dst * HC + c0;
                asm volatile("red.global.add.v4.f32 [%0], {%1, %2, %3, %4};"
                             :: "l"(op), "f"(nx), "f"(ny), "f"(nz), "f"(nw4)
                             : "memory");
                if ((lane & 3) == 0) {
                    float* dp = &g_sum[cur_dst * HH + head];
                    asm volatile("red.global.add.f32 [%0], %1;"
                                 :: "l"(dp), "f"(den) : "memory");
                }
            }
            cur_dst = dst;
            q4 = *(const float4*)&g_q[dst * HC + c0];
            nx = ny = nz = nw4 = den = 0.f;
        }

        float mea = (lane < ED) ? ea[eid * ED + lane] : 0.f;
        float ex = 0.f, ey = 0.f, ez = 0.f, ew = 0.f;
        #pragma unroll
        for (int t = 0; t < ED; t++) {
            float a = __shfl_sync(0xffffffffu, mea, t);
            ex += a * rw[t].x; ey += a * rw[t].y;
            ez += a * rw[t].z; ew += a * rw[t].w;
        }

        float4 k4 = *(const float4*)&g_k[src * HC + c0];
        float s = q4.x * (k4.x + ex) + q4.y * (k4.y + ey)
                + q4.z * (k4.z + ez) + q4.w * (k4.w + ew);
        s += __shfl_xor_sync(0xffffffffu, s, 1);
        s += __shfl_xor_sync(0xffffffffu, s, 2);

        float p = __expf(s * 0.25f);   // 1/sqrt(C), C=16

        float4 v4 = *(const float4*)&g_v[src * HC + c0];
        nx  += (v4.x + ex) * p;
        ny  += (v4.y + ey) * p;
        nz  += (v4.z + ez) * p;
        nw4 += (v4.w + ew) * p;
        den += p;
    }

    if (cur_dst >= 0) {
        float* op = g_attn + (size_t)cur_dst * HC + c0;
        asm volatile("red.global.add.v4.f32 [%0], {%1, %2, %3, %4};"
                     :: "l"(op), "f"(nx), "f"(ny), "f"(nz), "f"(nw4)
                     : "memory");
        if ((lane & 3) == 0) {
            float* dp = &g_sum[cur_dst * HH + head];
            asm volatile("red.global.add.f32 [%0], %1;"
                         :: "l"(dp), "f"(den) : "memory");
        }
    }
}

// ---------------------------------------------------------------------------
// Node-level normalize: out += num / (den + 1e-16). One float4 per thread.
// ---------------------------------------------------------------------------
__global__ __launch_bounds__(256) void normalize_kernel(float* __restrict__ out)
{
    int i = blockIdx.x * blockDim.x + threadIdx.x;
    int n4 = (NN * HC) / 4;
    if (i >= n4) return;
    int node = i >> 5;
    int head = (i & 31) >> 2;
    float inv = 1.f / (g_sum[node * HH + head] + 1e-16f);
    float4 a = ((const float4*)g_attn)[i];
    float4 o = ((float4*)out)[i];
    o.x += a.x * inv; o.y += a.y * inv;
    o.z += a.z * inv; o.w += a.w * inv;
    ((float4*)out)[i] = o;
}

// ---------------------------------------------------------------------------
extern "C" void kernel_launch(void* const* d_in, const int* in_sizes, int n_in,
                              void* d_out, int out_size)
{
    const float* x  = (const float*)d_in[0];
    const int*   ei = (const int*)d_in[1];
    const float* ea = (const float*)d_in[2];
    const float* wq = (const float*)d_in[3];
    const float* bq = (const float*)d_in[4];
    const float* wk = (const float*)d_in[5];
    const float* bk = (const float*)d_in[6];
    const float* wv = (const float*)d_in[7];
    const float* bv = (const float*)d_in[8];
    const float* we = (const float*)d_in[9];
    const float* ws = (const float*)d_in[10];
    const float* bs = (const float*)d_in[11];
    float* out = (float*)d_out;

    // zero + CSR build (by dst)
    zero_kernel<<<((NN * HC) / 4 + 255) / 256, 256>>>();
    hist_kernel<<<(EE + 255) / 256, 256>>>(ei);
    scan1_kernel<<<196, 256>>>();
    scan2_kernel<<<1, 256>>>();
    scan3_kernel<<<NPAD / 256, 256>>>();
    permute_kernel<<<(EE + 255) / 256, 256>>>(ei);

    // projections
    dim3 g0(391, 4);                       // ceil(50000/128) x 4 matrices
    gemm_kernel<<<g0, 256>>>(x, wq, bq, wk, bk, wv, bv, ws, bs, out);

    // attention: sorted scatter with run-length accumulation
    int warps = (EE + CHUNK - 1) / CHUNK;
    edge_sorted_kernel<<<(warps * 32 + 255) / 256, 256>>>(ea, we);

    normalize_kernel<<<((NN * HC) / 4 + 255) / 256, 256>>>(out);
}

// round 7
// speedup vs baseline: 1.4133x; 1.1895x over previous
#include <cuda_runtime.h>
#include <cuda_bf16.h>
#include <cstdint>

#define NN 50000
#define EE 800000
#define INF 128
#define HC 128
#define HH 8
#define ED 16

#define NPAD 50176            // 196 * 256, >= NN+1
#define CHUNK 16              // sorted edges per warp

// ---- scratch (device globals; no allocation allowed) ----
__device__ __align__(16) float g_q[NN * HC];
__device__ __align__(16) float g_k[NN * HC];
__device__ __align__(16) float g_v[NN * HC];
__device__ __align__(16) float g_attn[NN * HC];   // unnormalized numerator
__device__ __align__(16) float g_sum[NN * HH];    // softmax denominator
__device__ int g_cnt[NPAD];        // per-dst degree histogram (zero-padded)
__device__ int g_rowptr[NPAD];     // exclusive prefix sum
__device__ int g_wcnt[NN];         // write cursors for permute
__device__ int g_blk[256];         // per-block sums for scan
__device__ __align__(16) int4 g_sde[EE];  // (src, dst, eid) sorted by dst

// bf16 hi/lo scratch (rows padded to NPAD; pad rows stay zero => safe reads)
__device__ __align__(16) unsigned short g_xh[NPAD * INF];
__device__ __align__(16) unsigned short g_xl[NPAD * INF];
__device__ __align__(16) unsigned short g_wh[4][HC * INF];  // [n][k] layout
__device__ __align__(16) unsigned short g_wl[4][HC * INF];

// ---------------------------------------------------------------------------
__global__ void zero_kernel() {
    int i = blockIdx.x * blockDim.x + threadIdx.x;
    if (i < NPAD) g_cnt[i] = 0;
    int n4 = (NN * HC) / 4;
    if (i < n4) ((float4*)g_attn)[i] = make_float4(0.f, 0.f, 0.f, 0.f);
    if (i < NN * HH) g_sum[i] = 0.f;
}

__global__ void hist_kernel(const int* __restrict__ ei) {
    int e = blockIdx.x * blockDim.x + threadIdx.x;
    if (e < EE) atomicAdd(&g_cnt[ei[EE + e]], 1);
}

__global__ void scan1_kernel() {
    __shared__ int s[256];
    int t = threadIdx.x;
    int i = blockIdx.x * 256 + t;
    int v = g_cnt[i];
    s[t] = v;
    __syncthreads();
    #pragma unroll
    for (int off = 1; off < 256; off <<= 1) {
        int u = (t >= off) ? s[t - off] : 0;
        __syncthreads();
        s[t] += u;
        __syncthreads();
    }
    g_rowptr[i] = s[t] - v;
    if (t == 255) g_blk[blockIdx.x] = s[255];
}

__global__ void scan2_kernel() {
    __shared__ int s[256];
    int t = threadIdx.x;
    int v = (t < 196) ? g_blk[t] : 0;
    s[t] = v;
    __syncthreads();
    #pragma unroll
    for (int off = 1; off < 256; off <<= 1) {
        int u = (t >= off) ? s[t - off] : 0;
        __syncthreads();
        s[t] += u;
        __syncthreads();
    }
    if (t < 196) g_blk[t] = s[t] - v;
}

__global__ void scan3_kernel() {
    int i = blockIdx.x * blockDim.x + threadIdx.x;
    if (i < NPAD) {
        int v = g_rowptr[i] + g_blk[i >> 8];
        g_rowptr[i] = v;
        if (i < NN) g_wcnt[i] = v;
    }
}

__global__ void permute_kernel(const int* __restrict__ ei) {
    int e = blockIdx.x * blockDim.x + threadIdx.x;
    if (e < EE) {
        int src = ei[e];
        int dst = ei[EE + e];
        int pos = atomicAdd(&g_wcnt[dst], 1);
        g_sde[pos] = make_int4(src, dst, e, 0);
    }
}

// ---------------------------------------------------------------------------
// convert x (fp32 [m][k]) -> bf16 hi/lo, same layout
// ---------------------------------------------------------------------------
__global__ void convert_x_kernel(const float* __restrict__ x) {
    int i = blockIdx.x * blockDim.x + threadIdx.x;   // float4 index
    if (i >= (NN * INF) / 4) return;
    float4 v = ((const float4*)x)[i];
    float vv[4] = {v.x, v.y, v.z, v.w};
    unsigned short h[4], l[4];
    #pragma unroll
    for (int j = 0; j < 4; j++) {
        __nv_bfloat16 hb = __float2bfloat16(vv[j]);
        __nv_bfloat16 lb = __float2bfloat16(vv[j] - __bfloat162float(hb));
        h[j] = __bfloat16_as_ushort(hb);
        l[j] = __bfloat16_as_ushort(lb);
    }
    uint2 ph = make_uint2((uint32_t)h[0] | ((uint32_t)h[1] << 16),
                          (uint32_t)h[2] | ((uint32_t)h[3] << 16));
    uint2 pl = make_uint2((uint32_t)l[0] | ((uint32_t)l[1] << 16),
                          (uint32_t)l[2] | ((uint32_t)l[3] << 16));
    ((uint2*)g_xh)[i] = ph;
    ((uint2*)g_xl)[i] = pl;
}

// ---------------------------------------------------------------------------
// convert W (fp32 [k][n]) -> bf16 hi/lo, TRANSPOSED to [n][k]
// ---------------------------------------------------------------------------
__global__ void convert_w_kernel(
    const float* __restrict__ wq, const float* __restrict__ wk,
    const float* __restrict__ wv, const float* __restrict__ ws)
{
    int m = blockIdx.y;
    const float* W = (m == 0) ? wq : (m == 1) ? wk : (m == 2) ? wv : ws;
    int idx = blockIdx.x * 256 + threadIdx.x;  // 0..16383
    int n = idx & 127, k = idx >> 7;
    float v = W[k * HC + n];
    __nv_bfloat16 hb = __float2bfloat16(v);
    __nv_bfloat16 lb = __float2bfloat16(v - __bfloat162float(hb));
    g_wh[m][n * INF + k] = __bfloat16_as_ushort(hb);
    g_wl[m][n * INF + k] = __bfloat16_as_ushort(lb);
}

// ---------------------------------------------------------------------------
// HMMA GEMM: D = x@W + b for 4 matrices, bf16 hi/lo split (3 terms).
// CTA = 128x128 tile, 8 warps (2x4), warp tile 64x32, m16n8k16 atoms.
// A tile resident in smem across all 4 matrices.
// smem bf16 row stride 136 (272B) -> conflict-free fragment LDS.
// ---------------------------------------------------------------------------
#define ASTRIDE 272          // bytes per smem row (136 bf16)
#define SM_A_H  0            // 128*272 = 34816
#define SM_A_L  34816
#define SM_B_H  69632
#define SM_B_L  104448
#define SM_BIAS 139264       // 512 floats = 2048
#define SM_TOT  141312

__global__ __launch_bounds__(256, 1) void mma_gemm_kernel(
    const float* __restrict__ bq, const float* __restrict__ bk,
    const float* __restrict__ bv, const float* __restrict__ bs,
    float* __restrict__ out)
{
    extern __shared__ char sm[];
    int tid = threadIdx.x;
    int w = tid >> 5;
    int lane = tid & 31;
    int g = lane >> 2;        // 0..7
    int t = lane & 3;         // 0..3
    int mw = w >> 2;          // 0..1
    int nw = w & 3;           // 0..3
    int rowBase = blockIdx.x * 128;

    // ---- copy A tile (hi+lo) from bf16 scratch (pad rows are zero) ----
    #pragma unroll
    for (int i = 0; i < 8; i++) {
        int idx = tid + i * 256;          // 0..2047
        int r = idx >> 4;                 // row 0..127
        int kc = idx & 15;                // 8-bf16 chunk
        size_t src = ((size_t)(rowBase + r) * INF + kc * 8) * 2;
        *(uint4*)(sm + SM_A_H + r * ASTRIDE + kc * 16) =
            *(const uint4*)((const char*)g_xh + src);
        *(uint4*)(sm + SM_A_L + r * ASTRIDE + kc * 16) =
            *(const uint4*)((const char*)g_xl + src);
    }
    // biases
    for (int j = tid; j < 512; j += 256) {
        int m = j >> 7, c = j & 127;
        const float* B = (m == 0) ? bq : (m == 1) ? bk : (m == 2) ? bv : bs;
        *(float*)(sm + SM_BIAS + j * 4) = B[c];
    }

    for (int m = 0; m < 4; m++) {
        // ---- copy B tile [n][k] hi/lo ----
        __syncthreads();     // protect previous B from overwrite
        #pragma unroll
        for (int i = 0; i < 8; i++) {
            int idx = tid + i * 256;
            int n = idx >> 4;
            int kc = idx & 15;
            size_t src = ((size_t)n * INF + kc * 8) * 2;
            *(uint4*)(sm + SM_B_H + n * ASTRIDE + kc * 16) =
                *(const uint4*)((const char*)g_wh[m] + src);
            *(uint4*)(sm + SM_B_L + n * ASTRIDE + kc * 16) =
                *(const uint4*)((const char*)g_wl[m] + src);
        }
        __syncthreads();

        float acc[4][4][4];
        #pragma unroll
        for (int a = 0; a < 4; a++)
            #pragma unroll
            for (int b = 0; b < 4; b++)
                #pragma unroll
                for (int c = 0; c < 4; c++) acc[a][b][c] = 0.f;

        #pragma unroll
        for (int s = 0; s < 3; s++) {
            const char* Ab = sm + ((s == 2) ? SM_A_L : SM_A_H);
            const char* Bb = sm + ((s == 1) ? SM_B_L : SM_B_H);
            #pragma unroll
            for (int kt = 0; kt < 8; kt++) {
                int kb = (kt * 16 + t * 2) * 2;   // byte offset of k
                uint32_t bf[4][2];
                #pragma unroll
                for (int nt = 0; nt < 4; nt++) {
                    const char* p = Bb + (nw * 32 + nt * 8 + g) * ASTRIDE + kb;
                    bf[nt][0] = *(const uint32_t*)p;
                    bf[nt][1] = *(const uint32_t*)(p + 16);
                }
                #pragma unroll
                for (int mt = 0; mt < 4; mt++) {
                    const char* p = Ab + (mw * 64 + mt * 16 + g) * ASTRIDE + kb;
                    uint32_t a0 = *(const uint32_t*)p;
                    uint32_t a1 = *(const uint32_t*)(p + 8 * ASTRIDE);
                    uint32_t a2 = *(const uint32_t*)(p + 16);
                    uint32_t a3 = *(const uint32_t*)(p + 8 * ASTRIDE + 16);
                    #pragma unroll
                    for (int nt = 0; nt < 4; nt++) {
                        asm volatile(
                            "mma.sync.aligned.m16n8k16.row.col.f32.bf16.bf16.f32 "
                            "{%0,%1,%2,%3}, {%4,%5,%6,%7}, {%8,%9}, {%0,%1,%2,%3};"
                            : "+f"(acc[mt][nt][0]), "+f"(acc[mt][nt][1]),
                              "+f"(acc[mt][nt][2]), "+f"(acc[mt][nt][3])
                            : "r"(a0), "r"(a1), "r"(a2), "r"(a3),
                              "r"(bf[nt][0]), "r"(bf[nt][1]));
                    }
                }
            }
        }

        // ---- epilogue: D + bias -> output ----
        float* O = (m == 0) ? g_q : (m == 1) ? g_k : (m == 2) ? g_v : out;
        const float* sb = (const float*)(sm + SM_BIAS) + m * 128;
        #pragma unroll
        for (int mt = 0; mt < 4; mt++) {
            int r0 = rowBase + mw * 64 + mt * 16 + g;
            int r1 = r0 + 8;
            #pragma unroll
            for (int nt = 0; nt < 4; nt++) {
                int col = nw * 32 + nt * 8 + t * 2;
                float bx = sb[col], by = sb[col + 1];
                if (r0 < NN) {
                    float2 o0 = make_float2(acc[mt][nt][0] + bx,
                                            acc[mt][nt][1] + by);
                    *(float2*)&O[(size_t)r0 * HC + col] = o0;
                }
                if (r1 < NN) {
                    float2 o1 = make_float2(acc[mt][nt][2] + bx,
                                            acc[mt][nt][3] + by);
                    *(float2*)&O[(size_t)r1 * HC + col] = o1;
                }
            }
        }
    }
}

// ---------------------------------------------------------------------------
// Sorted-scatter edge kernel (unchanged from R6)
// ---------------------------------------------------------------------------
__global__ __launch_bounds__(256, 2) void edge_sorted_kernel(
    const float* __restrict__ ea,
    const float* __restrict__ we)
{
    int lane = threadIdx.x & 31;
    int w = (blockIdx.x * 256 + threadIdx.x) >> 5;
    int base = w * CHUNK;
    if (base >= EE) return;
    int end = (base + CHUNK < EE) ? base + CHUNK : EE;

    int c0 = lane << 2;
    int head = lane >> 2;

    float4 rw[ED];
    #pragma unroll
    for (int i = 0; i < ED; i++)
        rw[i] = *(const float4*)&we[i * HC + c0];

    int cur_dst = -1;
    float4 q4 = make_float4(0.f, 0.f, 0.f, 0.f);
    float nx = 0.f, ny = 0.f, nz = 0.f, nw4 = 0.f, den = 0.f;

    for (int i = base; i < end; i++) {
        int4 sde = g_sde[i];
        int src = sde.x, dst = sde.y, eid = sde.z;

        if (dst != cur_dst) {
            if (cur_dst >= 0) {
                float* op = g_attn + (size_t)cur_dst * HC + c0;
                asm volatile("red.global.add.v4.f32 [%0], {%1, %2, %3, %4};"
                             :: "l"(op), "f"(nx), "f"(ny), "f"(nz), "f"(nw4)
                             : "memory");
                if ((lane & 3) == 0) {
                    float* dp = &g_sum[cur_dst * HH + head];
                    asm volatile("red.global.add.f32 [%0], %1;"
                                 :: "l"(dp), "f"(den) : "memory");
                }
            }
            cur_dst = dst;
            q4 = *(const float4*)&g_q[dst * HC + c0];
            nx = ny = nz = nw4 = den = 0.f;
        }

        float mea = (lane < ED) ? ea[eid * ED + lane] : 0.f;
        float ex = 0.f, ey = 0.f, ez = 0.f, ew = 0.f;
        #pragma unroll
        for (int tt = 0; tt < ED; tt++) {
            float a = __shfl_sync(0xffffffffu, mea, tt);
            ex += a * rw[tt].x; ey += a * rw[tt].y;
            ez += a * rw[tt].z; ew += a * rw[tt].w;
        }

        float4 k4 = *(const float4*)&g_k[src * HC + c0];
        float s = q4.x * (k4.x + ex) + q4.y * (k4.y + ey)
                + q4.z * (k4.z + ez) + q4.w * (k4.w + ew);
        s += __shfl_xor_sync(0xffffffffu, s, 1);
        s += __shfl_xor_sync(0xffffffffu, s, 2);

        float p = __expf(s * 0.25f);

        float4 v4 = *(const float4*)&g_v[src * HC + c0];
        nx  += (v4.x + ex) * p;
        ny  += (v4.y + ey) * p;
        nz  += (v4.z + ez) * p;
        nw4 += (v4.w + ew) * p;
        den += p;
    }

    if (cur_dst >= 0) {
        float* op = g_attn + (size_t)cur_dst * HC + c0;
        asm volatile("red.global.add.v4.f32 [%0], {%1, %2, %3, %4};"
                     :: "l"(op), "f"(nx), "f"(ny), "f"(nz), "f"(nw4)
                     : "memory");
        if ((lane & 3) == 0) {
            float* dp = &g_sum[cur_dst * HH + head];
            asm volatile("red.global.add.f32 [%0], %1;"
                         :: "l"(dp), "f"(den) : "memory");
        }
    }
}

// ---------------------------------------------------------------------------
__global__ __launch_bounds__(256) void normalize_kernel(float* __restrict__ out)
{
    int i = blockIdx.x * blockDim.x + threadIdx.x;
    int n4 = (NN * HC) / 4;
    if (i >= n4) return;
    int node = i >> 5;
    int head = (i & 31) >> 2;
    float inv = 1.f / (g_sum[node * HH + head] + 1e-16f);
    float4 a = ((const float4*)g_attn)[i];
    float4 o = ((float4*)out)[i];
    o.x += a.x * inv; o.y += a.y * inv;
    o.z += a.z * inv; o.w += a.w * inv;
    ((float4*)out)[i] = o;
}

// ---------------------------------------------------------------------------
extern "C" void kernel_launch(void* const* d_in, const int* in_sizes, int n_in,
                              void* d_out, int out_size)
{
    const float* x  = (const float*)d_in[0];
    const int*   ei = (const int*)d_in[1];
    const float* ea = (const float*)d_in[2];
    const float* wq = (const float*)d_in[3];
    const float* bq = (const float*)d_in[4];
    const float* wk = (const float*)d_in[5];
    const float* bk = (const float*)d_in[6];
    const float* wv = (const float*)d_in[7];
    const float* bv = (const float*)d_in[8];
    const float* we = (const float*)d_in[9];
    const float* ws = (const float*)d_in[10];
    const float* bs = (const float*)d_in[11];
    float* out = (float*)d_out;

    static bool attr_set = false;
    if (!attr_set) {
        cudaFuncSetAttribute(mma_gemm_kernel,
                             cudaFuncAttributeMaxDynamicSharedMemorySize, SM_TOT);
        attr_set = true;
    }

    // zero + CSR build (by dst)
    zero_kernel<<<((NN * HC) / 4 + 255) / 256, 256>>>();
    hist_kernel<<<(EE + 255) / 256, 256>>>(ei);
    scan1_kernel<<<196, 256>>>();
    scan2_kernel<<<1, 256>>>();
    scan3_kernel<<<NPAD / 256, 256>>>();
    permute_kernel<<<(EE + 255) / 256, 256>>>(ei);

    // projections (tensor pipe)
    convert_x_kernel<<<((NN * INF) / 4 + 255) / 256, 256>>>(x);
    dim3 gw(64, 4);
    convert_w_kernel<<<gw, 256>>>(wq, wk, wv, ws);
    mma_gemm_kernel<<<391, 256, SM_TOT>>>(bq, bk, bv, bs, out);

    // attention: sorted scatter with run-length accumulation
    int warps = (EE + CHUNK - 1) / CHUNK;
    edge_sorted_kernel<<<(warps * 32 + 255) / 256, 256>>>(ea, we);

    normalize_kernel<<<((NN * HC) / 4 + 255) / 256, 256>>>(out);
}